// round 16
// baseline (speedup 1.0000x reference)
#include <cuda_runtime.h>
#include <cuda_fp16.h>
#include <math.h>
#include <stdint.h>

#define B_   2
#define T_   2048
#define E_   2048
#define HQ_  32
#define HKV_ 8
#define HD_  64
#define KVD_ 512
#define M_   4096
#define QKD3 3072   // E_ + 2*KVD_ : merged Q|K|V projection width

// ---------------------------------------------------------------------------
// Device scratch (pure fp16, all row-major)
// ---------------------------------------------------------------------------
__device__ __half g_xh[(size_t)M_*E_];
__device__ __half g_Wqkv[(size_t)E_*QKD3];     // [Wq*0.1803 | Wk | Wv]
__device__ __half g_Woh[(size_t)E_*E_];        // Wo [2048,2048]
__device__ __half g_QKV[(size_t)M_*QKD3];      // [Q*s | K | V]
__device__ __half g_Ah[(size_t)M_*E_];         // attention out

// ---------------------------------------------------------------------------
// Helpers
// ---------------------------------------------------------------------------
__device__ __forceinline__ uint32_t smem_u32(const void* p) {
    return (uint32_t)__cvta_generic_to_shared(p);
}
#define CP_ASYNC16(sa, ga) \
    asm volatile("cp.async.cg.shared.global [%0], [%1], 16;" :: "r"(sa), "l"(ga))
#define CP_COMMIT() asm volatile("cp.async.commit_group;" ::: "memory")
#define CP_WAIT0()  asm volatile("cp.async.wait_group 0;" ::: "memory")
#define CP_WAIT1()  asm volatile("cp.async.wait_group 1;" ::: "memory")

__device__ __forceinline__ void ldm_x4(uint32_t* r, uint32_t addr) {
    asm volatile("ldmatrix.sync.aligned.m8n8.x4.shared.b16 {%0,%1,%2,%3}, [%4];"
        : "=r"(r[0]), "=r"(r[1]), "=r"(r[2]), "=r"(r[3]) : "r"(addr));
}
__device__ __forceinline__ void ldm_x4t(uint32_t* r, uint32_t addr) {
    asm volatile("ldmatrix.sync.aligned.m8n8.x4.trans.shared.b16 {%0,%1,%2,%3}, [%4];"
        : "=r"(r[0]), "=r"(r[1]), "=r"(r[2]), "=r"(r[3]) : "r"(addr));
}
__device__ __forceinline__ void mma16816(float* c, const uint32_t* a, const uint32_t* b) {
    asm volatile("mma.sync.aligned.m16n8k16.row.col.f32.f16.f16.f32 "
        "{%0,%1,%2,%3}, {%4,%5,%6,%7}, {%8,%9}, {%0,%1,%2,%3};"
        : "+f"(c[0]), "+f"(c[1]), "+f"(c[2]), "+f"(c[3])
        : "r"(a[0]), "r"(a[1]), "r"(a[2]), "r"(a[3]), "r"(b[0]), "r"(b[1]));
}
__device__ __forceinline__ uint32_t pack_h(float a, float b) {
    uint32_t r;
    asm("cvt.rn.f16x2.f32 %0, %1, %2;" : "=r"(r) : "f"(b), "f"(a));
    return r;
}
__device__ __forceinline__ float ex2f(float x) {
    float r;
    asm("ex2.approx.ftz.f32 %0, %1;" : "=f"(r) : "f"(x));
    return r;
}

// ---------------------------------------------------------------------------
// GEMM superstage loaders (BK = 64, CTA tile 128 x 256)
// A: 128 rows x 64 cols fp16, row pitch 144B
// B: 64 rows x 256 cols fp16, row pitch 528B (528 mod 128 = 16: conflict-free)
// ---------------------------------------------------------------------------
#define GA2  18432            // 128*144
#define GB2  33792            // 64*528
#define GSS2 (GA2 + GB2)      // 52224 per superstage

__device__ __forceinline__ void stage_a2(uint32_t sdst, const __half* __restrict__ g,
                                         int ld, int tid) {
#pragma unroll
    for (int i = 0; i < 4; i++) {
        int idx = tid + i * 256;
        int r = idx >> 3, q = idx & 7;
        CP_ASYNC16(sdst + r * 144 + q * 16, g + (size_t)r * ld + q * 8);
    }
}
__device__ __forceinline__ void stage_b2(uint32_t sdst, const __half* __restrict__ g,
                                         int ld, int tid) {
#pragma unroll
    for (int i = 0; i < 8; i++) {
        int idx = tid + i * 256;
        int r = idx >> 5, q = idx & 31;
        CP_ASYNC16(sdst + r * 528 + q * 16, g + (size_t)r * ld + q * 8);
    }
}

// ---------------------------------------------------------------------------
// Warp-MMA GEMM, pure fp16, 1 CTA/SM, 255 regs, CTA 128x256, warp tile 64x64.
// Double-buffered BK=64 superstages; one barrier per 4 k16-steps.
// OUT: 0 = fp32 + bias, 2 = fp16.  nit = K / 64.
// ---------------------------------------------------------------------------
template<int OUT>
__global__ __launch_bounds__(256, 1) void gemm_mma(
    const __half* __restrict__ Ah_, const __half* __restrict__ Bh_,
    int lda, int ldb, int nit,
    float* Cf, const float* bias, __half* Ch, int ldc)
{
    extern __shared__ char smem[];
    const uint32_t sb = smem_u32(smem);
    const int tid = threadIdx.x, wid = tid >> 5, lane = tid & 31;
    const int wm = wid & 1, wn = wid >> 1;

    const int row0 = blockIdx.y * 128;
    const int col0 = blockIdx.x * 256;

    const __half* gA = Ah_ + (size_t)row0 * lda;
    const __half* gB = Bh_ + col0;

    float acc[4][8][4];
#pragma unroll
    for (int i = 0; i < 4; i++)
#pragma unroll
        for (int j = 0; j < 8; j++)
#pragma unroll
            for (int c = 0; c < 4; c++) acc[i][j][c] = 0.f;

    // prologue: superstage 0 into buffer 0
    stage_a2(sb,       gA, lda, tid);
    stage_b2(sb + GA2, gB, ldb, tid);
    CP_COMMIT();

    const uint32_t aRow = (uint32_t)(wm * 64 + (lane & 15)) * 144 + (lane >> 4) * 16;
    const uint32_t bOff = (uint32_t)((lane & 7) + (lane & 8)) * 528
                        + wn * 128 + (lane >> 4) * 16;

    for (int it = 0; it < nit; it++) {
        CP_WAIT0();
        __syncthreads();

        if (it + 1 < nit) {
            const uint32_t sn = sb + ((it + 1) & 1) * GSS2;
            stage_a2(sn,       gA + (it + 1) * 64, lda, tid);
            stage_b2(sn + GA2, gB + (size_t)(it + 1) * 64 * ldb, ldb, tid);
            CP_COMMIT();
        }

        const uint32_t sa = sb + (it & 1) * GSS2 + aRow;
        const uint32_t sbv = sb + (it & 1) * GSS2 + GA2 + bOff;
#pragma unroll
        for (int ks = 0; ks < 4; ks++) {
            uint32_t ah[4][4];
#pragma unroll
            for (int mt = 0; mt < 4; mt++)
                ldm_x4(ah[mt], sa + mt * 16 * 144 + ks * 32);
#pragma unroll
            for (int p = 0; p < 4; p++) {
                uint32_t bh4[4];
                ldm_x4t(bh4, sbv + ks * (16 * 528) + p * 32);
#pragma unroll
                for (int mt = 0; mt < 4; mt++) {
                    mma16816(acc[mt][2 * p],     ah[mt], bh4);
                    mma16816(acc[mt][2 * p + 1], ah[mt], bh4 + 2);
                }
            }
        }
    }

    const int rw = lane >> 2, cw = (lane & 3) * 2;
#pragma unroll
    for (int mt = 0; mt < 4; mt++) {
#pragma unroll
        for (int nt = 0; nt < 8; nt++) {
            const int rg = row0 + wm * 64 + mt * 16 + rw;
            const int cg = col0 + wn * 64 + nt * 8 + cw;
            float v0 = acc[mt][nt][0], v1 = acc[mt][nt][1];
            float v2 = acc[mt][nt][2], v3 = acc[mt][nt][3];
            size_t i0 = (size_t)rg * ldc + cg;
            size_t i1 = (size_t)(rg + 8) * ldc + cg;
            if (OUT == 0) {
                float b0 = bias[cg], b1 = bias[cg + 1];
                *reinterpret_cast<float2*>(Cf + i0) = make_float2(v0 + b0, v1 + b1);
                *reinterpret_cast<float2*>(Cf + i1) = make_float2(v2 + b0, v3 + b1);
            } else {
                *reinterpret_cast<uint32_t*>(Ch + i0) = pack_h(v0, v1);
                *reinterpret_cast<uint32_t*>(Ch + i1) = pack_h(v2, v3);
            }
        }
    }
}

// ---------------------------------------------------------------------------
// Fused flash attention (unchanged from R14): no-max exp2 softmax, 3-stage
// KV ring, one barrier per KV tile. 128q x 1 head, 8 warps, 2 CTAs/SM.
// ---------------------------------------------------------------------------
#define KROW 144
#define KTB (128 * KROW)          // 18432
#define FSTG (2 * KTB)            // 36864

__device__ __forceinline__ void kv_load(uint32_t dst,
    const __half* __restrict__ gK, const __half* __restrict__ gV,
    int kt, int tid)
{
#pragma unroll
    for (int i = 0; i < 4; i++) {
        int idx = tid + i * 256;
        int r = idx >> 3, q = idx & 7;
        size_t src = (size_t)(kt * 128 + r) * QKD3 + q * 8;
        CP_ASYNC16(dst + r * KROW + q * 16, gK + src);
        CP_ASYNC16(dst + KTB + r * KROW + q * 16, gV + src);
    }
}

__global__ __launch_bounds__(256, 2) void flash_attn(
    const __half* __restrict__ QKV_, __half* __restrict__ Ah)
{
    extern __shared__ char smem[];
    const uint32_t sb = smem_u32(smem);
    const int tid = threadIdx.x, wid = tid >> 5, lane = tid & 31;
    const int q0 = blockIdx.x * 128, hq = blockIdx.y, b = blockIdx.z;
    const int hkv = hq >> 2;

    const __half* gQ = QKV_ + (size_t)(b * T_ + q0) * QKD3 + hq * HD_;
    const __half* gK = QKV_ + (size_t)(b * T_) * QKD3 + E_ + hkv * HD_;
    const __half* gV = QKV_ + (size_t)(b * T_) * QKD3 + E_ + KVD_ + hkv * HD_;

#pragma unroll
    for (int i = 0; i < 4; i++) {
        int idx = tid + i * 256, r = idx >> 3, q = idx & 7;
        CP_ASYNC16(sb + r * KROW + q * 16, gQ + (size_t)r * QKD3 + q * 8);
    }
    CP_COMMIT();
    CP_WAIT0();
    __syncthreads();

    uint32_t qh[4][4];
    {
        uint32_t qb = sb + (uint32_t)(wid * 16 + (lane & 15)) * KROW + (lane >> 4) * 16;
#pragma unroll
        for (int ks = 0; ks < 4; ks++)
            ldm_x4(qh[ks], qb + ks * 32);
    }
    __syncthreads();

    kv_load(sb,        gK, gV, 0, tid);
    CP_COMMIT();
    kv_load(sb + FSTG, gK, gV, 1, tid);
    CP_COMMIT();

    float o[8][4];
#pragma unroll
    for (int j = 0; j < 8; j++)
#pragma unroll
        for (int c = 0; c < 4; c++) o[j][c] = 0.f;
    float l0 = 0.f, l1 = 0.f;

    const uint32_t kOff = ((lane & 7) + (lane >> 4) * 8) * KROW + ((lane >> 3) & 1) * 16;
    const uint32_t vOff = (uint32_t)((lane & 7) + (lane & 8)) * KROW + (lane >> 4) * 16;

    int s_cur = 0, s_nxt = 2;
    for (int kt = 0; kt < 16; kt++) {
        if (kt < 15) { CP_WAIT1(); } else { CP_WAIT0(); }
        __syncthreads();

        if (kt + 2 < 16) {
            kv_load(sb + s_nxt * FSTG, gK, gV, kt + 2, tid);
            CP_COMMIT();
        }

        const uint32_t cur = sb + s_cur * FSTG;
        const uint32_t kb = cur + kOff;
        const uint32_t vb = cur + KTB + vOff;

#pragma unroll
        for (int h = 0; h < 2; h++) {
            float s[8][4];
#pragma unroll
            for (int j = 0; j < 8; j++)
#pragma unroll
                for (int c = 0; c < 4; c++) s[j][c] = 0.f;

#pragma unroll
            for (int ks = 0; ks < 4; ks++) {
#pragma unroll
                for (int p = 0; p < 4; p++) {
                    uint32_t kh4[4];
                    ldm_x4(kh4, kb + (h * 4 + p) * (16 * KROW) + ks * 32);
                    mma16816(s[2 * p],     qh[ks], kh4);
                    mma16816(s[2 * p + 1], qh[ks], kh4 + 2);
                }
            }

#pragma unroll
            for (int j = 0; j < 8; j++) {
                s[j][0] = ex2f(s[j][0]);
                s[j][1] = ex2f(s[j][1]);
                s[j][2] = ex2f(s[j][2]);
                s[j][3] = ex2f(s[j][3]);
                l0 += s[j][0] + s[j][1];
                l1 += s[j][2] + s[j][3];
            }

#pragma unroll
            for (int ks = 0; ks < 4; ks++) {
                uint32_t ph[4];
                ph[0] = pack_h(s[2 * ks][0],     s[2 * ks][1]);
                ph[1] = pack_h(s[2 * ks][2],     s[2 * ks][3]);
                ph[2] = pack_h(s[2 * ks + 1][0], s[2 * ks + 1][1]);
                ph[3] = pack_h(s[2 * ks + 1][2], s[2 * ks + 1][3]);
                const uint32_t vrow = vb + (h * 64 + ks * 16) * KROW;
#pragma unroll
                for (int p = 0; p < 4; p++) {
                    uint32_t vh4[4];
                    ldm_x4t(vh4, vrow + p * 32);
                    mma16816(o[2 * p],     ph, vh4);
                    mma16816(o[2 * p + 1], ph, vh4 + 2);
                }
            }
        }
        s_cur = (s_cur == 2) ? 0 : s_cur + 1;
        s_nxt = (s_nxt == 2) ? 0 : s_nxt + 1;
    }

    l0 += __shfl_xor_sync(~0u, l0, 1);
    l0 += __shfl_xor_sync(~0u, l0, 2);
    l1 += __shfl_xor_sync(~0u, l1, 1);
    l1 += __shfl_xor_sync(~0u, l1, 2);
    const float inv0 = 1.f / l0, inv1 = 1.f / l1;
    const int r0 = b * T_ + q0 + wid * 16 + (lane >> 2);
    const int cb = hq * HD_ + (lane & 3) * 2;
#pragma unroll
    for (int j = 0; j < 8; j++) {
        size_t i0 = (size_t)r0 * E_ + cb + 8 * j;
        size_t i1 = (size_t)(r0 + 8) * E_ + cb + 8 * j;
        *reinterpret_cast<uint32_t*>(Ah + i0) = pack_h(o[j][0] * inv0, o[j][1] * inv0);
        *reinterpret_cast<uint32_t*>(Ah + i1) = pack_h(o[j][2] * inv1, o[j][3] * inv1);
    }
}

// ---------------------------------------------------------------------------
// Prep: ONE kernel converts all weights + x; grid-stride, 4 float4 per thread
// for MLP=4 (latency-bound kernel).
// ---------------------------------------------------------------------------
#define G_WQ 1048576u
#define G_WK (G_WQ + 262144u)
#define G_WV (G_WK + 262144u)
#define G_WO (G_WV + 1048576u)
#define G_X  (G_WO + 2097152u)
#define NCONV_TH (G_X / 4)            // 1441792 threads

__global__ void conv_all(const float* __restrict__ Wq, const float* __restrict__ Wk,
                         const float* __restrict__ Wv, const float* __restrict__ Wo,
                         const float* __restrict__ x,
                         __half* __restrict__ Wqkv, __half* __restrict__ Woh,
                         __half* __restrict__ xh, float qscale)
{
    uint32_t t = blockIdx.x * blockDim.x + threadIdx.x;
#pragma unroll
    for (int i = 0; i < 4; i++) {
        uint32_t g = t + (uint32_t)i * NCONV_TH;
        const float* src;
        __half* dst;
        uint32_t r, c;
        float sc = 1.f;
        if (g < G_WQ) {
            src = Wq + (size_t)g * 4;
            r = g >> 9; c = (g & 511) * 4;
            dst = Wqkv + (size_t)r * QKD3 + c;
            sc = qscale;
        } else if (g < G_WK) {
            uint32_t g2 = g - G_WQ;
            src = Wk + (size_t)g2 * 4;
            r = g2 >> 7; c = (g2 & 127) * 4;
            dst = Wqkv + (size_t)r * QKD3 + E_ + c;
        } else if (g < G_WV) {
            uint32_t g2 = g - G_WK;
            src = Wv + (size_t)g2 * 4;
            r = g2 >> 7; c = (g2 & 127) * 4;
            dst = Wqkv + (size_t)r * QKD3 + E_ + KVD_ + c;
        } else if (g < G_WO) {
            uint32_t g2 = g - G_WV;
            src = Wo + (size_t)g2 * 4;
            dst = Woh + (size_t)g2 * 4;
        } else {
            uint32_t g2 = g - G_WO;
            src = x + (size_t)g2 * 4;
            dst = xh + (size_t)g2 * 4;
        }
        float4 v = *reinterpret_cast<const float4*>(src);
        *reinterpret_cast<uint2*>(dst) =
            make_uint2(pack_h(v.x * sc, v.y * sc), pack_h(v.z * sc, v.w * sc));
    }
}

// ---------------------------------------------------------------------------
extern "C" void kernel_launch(void* const* d_in, const int* in_sizes, int n_in,
                              void* d_out, int out_size)
{
    const float* x  = (const float*)d_in[0];
    const float* Wq = (const float*)d_in[1];
    const float* Wk = (const float*)d_in[2];
    const float* Wv = (const float*)d_in[3];
    const float* Wo = (const float*)d_in[4];
    const float* bo = (const float*)d_in[5];
    float* out = (float*)d_out;

    __half *xh, *Wqkv, *Woh, *QKV, *Ah;
    cudaGetSymbolAddress((void**)&xh,   g_xh);
    cudaGetSymbolAddress((void**)&Wqkv, g_Wqkv);
    cudaGetSymbolAddress((void**)&Woh,  g_Woh);
    cudaGetSymbolAddress((void**)&QKV,  g_QKV);
    cudaGetSymbolAddress((void**)&Ah,   g_Ah);

    const int SMG = 2 * GSS2;   // 104448 -> 1 CTA/SM (255 regs)
    const int SMF = 3 * FSTG;   // 110592 -> 2 CTAs/SM
    cudaFuncSetAttribute(gemm_mma<0>, cudaFuncAttributeMaxDynamicSharedMemorySize, SMG);
    cudaFuncSetAttribute(gemm_mma<2>, cudaFuncAttributeMaxDynamicSharedMemorySize, SMG);
    cudaFuncSetAttribute(flash_attn, cudaFuncAttributeMaxDynamicSharedMemorySize, SMF);

    const float QSCALE = 0.125f * 1.44269504088896f;

    conv_all<<<NCONV_TH / 256, 256>>>(Wq, Wk, Wv, Wo, x, Wqkv, Woh, xh, QSCALE);

    // [Q|K|V] = x @ [Wq*s | Wk | Wv]  -> [4096, 3072]
    gemm_mma<2><<<dim3(QKD3 / 256, M_ / 128), 256, SMG>>>(
        xh, Wqkv, E_, QKD3, E_ / 64, nullptr, nullptr, QKV, QKD3);

    // fused attention -> Ah
    flash_attn<<<dim3(T_ / 128, HQ_, B_), 256, SMF>>>(QKV, Ah);

    // out = A @ Wo + bo
    gemm_mma<0><<<dim3(E_ / 256, M_ / 128), 256, SMG>>>(
        Ah, Woh, E_, E_, E_ / 64, out, bo, nullptr, E_);
}

// round 17
// speedup vs baseline: 1.0159x; 1.0159x over previous
#include <cuda_runtime.h>
#include <cuda_fp16.h>
#include <math.h>
#include <stdint.h>

#define B_   2
#define T_   2048
#define E_   2048
#define HQ_  32
#define HKV_ 8
#define HD_  64
#define KVD_ 512
#define M_   4096
#define QKD3 3072   // E_ + 2*KVD_ : merged Q|K|V projection width

// ---------------------------------------------------------------------------
// Device scratch (pure fp16, all row-major)
// ---------------------------------------------------------------------------
__device__ __half g_xh[(size_t)M_*E_];
__device__ __half g_Wqkv[(size_t)E_*QKD3];     // [Wq*0.1803 | Wk | Wv]
__device__ __half g_Woh[(size_t)E_*E_];        // Wo [2048,2048]
__device__ __half g_QKV[(size_t)M_*QKD3];      // [Q*s | K | V]
__device__ __half g_Ah[(size_t)M_*E_];         // attention out

// ---------------------------------------------------------------------------
// Helpers
// ---------------------------------------------------------------------------
__device__ __forceinline__ uint32_t smem_u32(const void* p) {
    return (uint32_t)__cvta_generic_to_shared(p);
}
#define CP_ASYNC16(sa, ga) \
    asm volatile("cp.async.cg.shared.global [%0], [%1], 16;" :: "r"(sa), "l"(ga))
#define CP_COMMIT() asm volatile("cp.async.commit_group;" ::: "memory")
#define CP_WAIT0()  asm volatile("cp.async.wait_group 0;" ::: "memory")
#define CP_WAIT1()  asm volatile("cp.async.wait_group 1;" ::: "memory")

__device__ __forceinline__ void ldm_x4(uint32_t* r, uint32_t addr) {
    asm volatile("ldmatrix.sync.aligned.m8n8.x4.shared.b16 {%0,%1,%2,%3}, [%4];"
        : "=r"(r[0]), "=r"(r[1]), "=r"(r[2]), "=r"(r[3]) : "r"(addr));
}
__device__ __forceinline__ void ldm_x4t(uint32_t* r, uint32_t addr) {
    asm volatile("ldmatrix.sync.aligned.m8n8.x4.trans.shared.b16 {%0,%1,%2,%3}, [%4];"
        : "=r"(r[0]), "=r"(r[1]), "=r"(r[2]), "=r"(r[3]) : "r"(addr));
}
__device__ __forceinline__ void mma16816(float* c, const uint32_t* a, const uint32_t* b) {
    asm volatile("mma.sync.aligned.m16n8k16.row.col.f32.f16.f16.f32 "
        "{%0,%1,%2,%3}, {%4,%5,%6,%7}, {%8,%9}, {%0,%1,%2,%3};"
        : "+f"(c[0]), "+f"(c[1]), "+f"(c[2]), "+f"(c[3])
        : "r"(a[0]), "r"(a[1]), "r"(a[2]), "r"(a[3]), "r"(b[0]), "r"(b[1]));
}
__device__ __forceinline__ uint32_t pack_h(float a, float b) {
    uint32_t r;
    asm("cvt.rn.f16x2.f32 %0, %1, %2;" : "=r"(r) : "f"(b), "f"(a));
    return r;
}
__device__ __forceinline__ float ex2f(float x) {
    float r;
    asm("ex2.approx.ftz.f32 %0, %1;" : "=f"(r) : "f"(x));
    return r;
}

// ---------------------------------------------------------------------------
// GEMM superstage (BK = 64, CTA tile 128 x 256, 512 threads)
// A: 128 rows x 64 cols fp16, row pitch 144B  (18432 B)
// B: 64 rows x 256 cols fp16, row pitch 528B  (33792 B)
// 4-stage ring; barrier every TWO superstages (128 HMMA/warp per window).
// ---------------------------------------------------------------------------
#define GA2  18432
#define GB2  33792
#define GSS2 (GA2 + GB2)      // 52224 per superstage

__device__ __forceinline__ void stage_a2(uint32_t sdst, const __half* __restrict__ g,
                                         int ld, int tid) {
#pragma unroll
    for (int i = 0; i < 2; i++) {
        int idx = tid + i * 512;
        int r = idx >> 3, q = idx & 7;
        CP_ASYNC16(sdst + r * 144 + q * 16, g + (size_t)r * ld + q * 8);
    }
}
__device__ __forceinline__ void stage_b2(uint32_t sdst, const __half* __restrict__ g,
                                         int ld, int tid) {
#pragma unroll
    for (int i = 0; i < 4; i++) {
        int idx = tid + i * 512;
        int r = idx >> 5, q = idx & 31;
        CP_ASYNC16(sdst + r * 528 + q * 16, g + (size_t)r * ld + q * 8);
    }
}

// ---------------------------------------------------------------------------
// Warp-MMA GEMM: 512 threads (16 warps, 4x4), warp tile 32 x 64, 1 CTA/SM.
// OUT: 0 = fp32 + bias, 2 = fp16.  nit = K / 64 (must be even).
// ---------------------------------------------------------------------------
template<int OUT>
__global__ __launch_bounds__(512, 1) void gemm_mma(
    const __half* __restrict__ Ah_, const __half* __restrict__ Bh_,
    int lda, int ldb, int nit,
    float* Cf, const float* bias, __half* Ch, int ldc)
{
    extern __shared__ char smem[];
    const uint32_t sb = smem_u32(smem);
    const int tid = threadIdx.x, wid = tid >> 5, lane = tid & 31;
    const int wm = wid & 3, wn = wid >> 2;   // 4 x 4 warp grid

    const int row0 = blockIdx.y * 128;
    const int col0 = blockIdx.x * 256;

    const __half* gA = Ah_ + (size_t)row0 * lda;
    const __half* gB = Bh_ + col0;

    float acc[2][8][4];
#pragma unroll
    for (int i = 0; i < 2; i++)
#pragma unroll
        for (int j = 0; j < 8; j++)
#pragma unroll
            for (int c = 0; c < 4; c++) acc[i][j][c] = 0.f;

    // prologue: superstages 0 and 1
    stage_a2(sb,              gA,      lda, tid);
    stage_b2(sb + GA2,        gB,      ldb, tid);
    CP_COMMIT();
    stage_a2(sb + GSS2,       gA + 64, lda, tid);
    stage_b2(sb + GSS2 + GA2, gB + (size_t)64 * ldb, ldb, tid);
    CP_COMMIT();

    const uint32_t aRow = (uint32_t)(wm * 32 + (lane & 15)) * 144 + (lane >> 4) * 16;
    const uint32_t bOff = (uint32_t)((lane & 7) + (lane & 8)) * 528
                        + wn * 128 + (lane >> 4) * 16;

    const int nw = nit >> 1;   // windows of 2 superstages
    for (int w = 0; w < nw; w++) {
        CP_WAIT0();
        __syncthreads();   // superstages 2w, 2w+1 resident; bufs (2w+2)&3,(2w+3)&3 free

        if (w + 1 < nw) {
            const int it2 = 2 * w + 2, it3 = 2 * w + 3;
            uint32_t s2 = sb + (it2 & 3) * GSS2;
            stage_a2(s2,       gA + it2 * 64, lda, tid);
            stage_b2(s2 + GA2, gB + (size_t)it2 * 64 * ldb, ldb, tid);
            CP_COMMIT();
            uint32_t s3 = sb + (it3 & 3) * GSS2;
            stage_a2(s3,       gA + it3 * 64, lda, tid);
            stage_b2(s3 + GA2, gB + (size_t)it3 * 64 * ldb, ldb, tid);
            CP_COMMIT();
        }

#pragma unroll
        for (int half = 0; half < 2; half++) {
            const int it = 2 * w + half;
            const uint32_t sa = sb + (it & 3) * GSS2 + aRow;
            const uint32_t sbv = sb + (it & 3) * GSS2 + GA2 + bOff;
#pragma unroll
            for (int ks = 0; ks < 4; ks++) {
                uint32_t ah[2][4];
#pragma unroll
                for (int mt = 0; mt < 2; mt++)
                    ldm_x4(ah[mt], sa + mt * 16 * 144 + ks * 32);
#pragma unroll
                for (int p = 0; p < 4; p++) {
                    uint32_t bh4[4];
                    ldm_x4t(bh4, sbv + ks * (16 * 528) + p * 32);
#pragma unroll
                    for (int mt = 0; mt < 2; mt++) {
                        mma16816(acc[mt][2 * p],     ah[mt], bh4);
                        mma16816(acc[mt][2 * p + 1], ah[mt], bh4 + 2);
                    }
                }
            }
        }
    }

    const int rw = lane >> 2, cw = (lane & 3) * 2;
#pragma unroll
    for (int mt = 0; mt < 2; mt++) {
#pragma unroll
        for (int nt = 0; nt < 8; nt++) {
            const int rg = row0 + wm * 32 + mt * 16 + rw;
            const int cg = col0 + wn * 64 + nt * 8 + cw;
            float v0 = acc[mt][nt][0], v1 = acc[mt][nt][1];
            float v2 = acc[mt][nt][2], v3 = acc[mt][nt][3];
            size_t i0 = (size_t)rg * ldc + cg;
            size_t i1 = (size_t)(rg + 8) * ldc + cg;
            if (OUT == 0) {
                float b0 = bias[cg], b1 = bias[cg + 1];
                *reinterpret_cast<float2*>(Cf + i0) = make_float2(v0 + b0, v1 + b1);
                *reinterpret_cast<float2*>(Cf + i1) = make_float2(v2 + b0, v3 + b1);
            } else {
                *reinterpret_cast<uint32_t*>(Ch + i0) = pack_h(v0, v1);
                *reinterpret_cast<uint32_t*>(Ch + i1) = pack_h(v2, v3);
            }
        }
    }
}

// ---------------------------------------------------------------------------
// Fused flash attention (unchanged from R14): no-max exp2 softmax, 3-stage
// KV ring, one barrier per KV tile. 128q x 1 head, 8 warps, 2 CTAs/SM.
// ---------------------------------------------------------------------------
#define KROW 144
#define KTB (128 * KROW)          // 18432
#define FSTG (2 * KTB)            // 36864

__device__ __forceinline__ void kv_load(uint32_t dst,
    const __half* __restrict__ gK, const __half* __restrict__ gV,
    int kt, int tid)
{
#pragma unroll
    for (int i = 0; i < 4; i++) {
        int idx = tid + i * 256;
        int r = idx >> 3, q = idx & 7;
        size_t src = (size_t)(kt * 128 + r) * QKD3 + q * 8;
        CP_ASYNC16(dst + r * KROW + q * 16, gK + src);
        CP_ASYNC16(dst + KTB + r * KROW + q * 16, gV + src);
    }
}

__global__ __launch_bounds__(256, 2) void flash_attn(
    const __half* __restrict__ QKV_, __half* __restrict__ Ah)
{
    extern __shared__ char smem[];
    const uint32_t sb = smem_u32(smem);
    const int tid = threadIdx.x, wid = tid >> 5, lane = tid & 31;
    const int q0 = blockIdx.x * 128, hq = blockIdx.y, b = blockIdx.z;
    const int hkv = hq >> 2;

    const __half* gQ = QKV_ + (size_t)(b * T_ + q0) * QKD3 + hq * HD_;
    const __half* gK = QKV_ + (size_t)(b * T_) * QKD3 + E_ + hkv * HD_;
    const __half* gV = QKV_ + (size_t)(b * T_) * QKD3 + E_ + KVD_ + hkv * HD_;

#pragma unroll
    for (int i = 0; i < 4; i++) {
        int idx = tid + i * 256, r = idx >> 3, q = idx & 7;
        CP_ASYNC16(sb + r * KROW + q * 16, gQ + (size_t)r * QKD3 + q * 8);
    }
    CP_COMMIT();
    CP_WAIT0();
    __syncthreads();

    uint32_t qh[4][4];
    {
        uint32_t qb = sb + (uint32_t)(wid * 16 + (lane & 15)) * KROW + (lane >> 4) * 16;
#pragma unroll
        for (int ks = 0; ks < 4; ks++)
            ldm_x4(qh[ks], qb + ks * 32);
    }
    __syncthreads();

    kv_load(sb,        gK, gV, 0, tid);
    CP_COMMIT();
    kv_load(sb + FSTG, gK, gV, 1, tid);
    CP_COMMIT();

    float o[8][4];
#pragma unroll
    for (int j = 0; j < 8; j++)
#pragma unroll
        for (int c = 0; c < 4; c++) o[j][c] = 0.f;
    float l0 = 0.f, l1 = 0.f;

    const uint32_t kOff = ((lane & 7) + (lane >> 4) * 8) * KROW + ((lane >> 3) & 1) * 16;
    const uint32_t vOff = (uint32_t)((lane & 7) + (lane & 8)) * KROW + (lane >> 4) * 16;

    int s_cur = 0, s_nxt = 2;
    for (int kt = 0; kt < 16; kt++) {
        if (kt < 15) { CP_WAIT1(); } else { CP_WAIT0(); }
        __syncthreads();

        if (kt + 2 < 16) {
            kv_load(sb + s_nxt * FSTG, gK, gV, kt + 2, tid);
            CP_COMMIT();
        }

        const uint32_t cur = sb + s_cur * FSTG;
        const uint32_t kb = cur + kOff;
        const uint32_t vb = cur + KTB + vOff;

#pragma unroll
        for (int h = 0; h < 2; h++) {
            float s[8][4];
#pragma unroll
            for (int j = 0; j < 8; j++)
#pragma unroll
                for (int c = 0; c < 4; c++) s[j][c] = 0.f;

#pragma unroll
            for (int ks = 0; ks < 4; ks++) {
#pragma unroll
                for (int p = 0; p < 4; p++) {
                    uint32_t kh4[4];
                    ldm_x4(kh4, kb + (h * 4 + p) * (16 * KROW) + ks * 32);
                    mma16816(s[2 * p],     qh[ks], kh4);
                    mma16816(s[2 * p + 1], qh[ks], kh4 + 2);
                }
            }

#pragma unroll
            for (int j = 0; j < 8; j++) {
                s[j][0] = ex2f(s[j][0]);
                s[j][1] = ex2f(s[j][1]);
                s[j][2] = ex2f(s[j][2]);
                s[j][3] = ex2f(s[j][3]);
                l0 += s[j][0] + s[j][1];
                l1 += s[j][2] + s[j][3];
            }

#pragma unroll
            for (int ks = 0; ks < 4; ks++) {
                uint32_t ph[4];
                ph[0] = pack_h(s[2 * ks][0],     s[2 * ks][1]);
                ph[1] = pack_h(s[2 * ks][2],     s[2 * ks][3]);
                ph[2] = pack_h(s[2 * ks + 1][0], s[2 * ks + 1][1]);
                ph[3] = pack_h(s[2 * ks + 1][2], s[2 * ks + 1][3]);
                const uint32_t vrow = vb + (h * 64 + ks * 16) * KROW;
#pragma unroll
                for (int p = 0; p < 4; p++) {
                    uint32_t vh4[4];
                    ldm_x4t(vh4, vrow + p * 32);
                    mma16816(o[2 * p],     ph, vh4);
                    mma16816(o[2 * p + 1], ph, vh4 + 2);
                }
            }
        }
        s_cur = (s_cur == 2) ? 0 : s_cur + 1;
        s_nxt = (s_nxt == 2) ? 0 : s_nxt + 1;
    }

    l0 += __shfl_xor_sync(~0u, l0, 1);
    l0 += __shfl_xor_sync(~0u, l0, 2);
    l1 += __shfl_xor_sync(~0u, l1, 1);
    l1 += __shfl_xor_sync(~0u, l1, 2);
    const float inv0 = 1.f / l0, inv1 = 1.f / l1;
    const int r0 = b * T_ + q0 + wid * 16 + (lane >> 2);
    const int cb = hq * HD_ + (lane & 3) * 2;
#pragma unroll
    for (int j = 0; j < 8; j++) {
        size_t i0 = (size_t)r0 * E_ + cb + 8 * j;
        size_t i1 = (size_t)(r0 + 8) * E_ + cb + 8 * j;
        *reinterpret_cast<uint32_t*>(Ah + i0) = pack_h(o[j][0] * inv0, o[j][1] * inv0);
        *reinterpret_cast<uint32_t*>(Ah + i1) = pack_h(o[j][2] * inv1, o[j][3] * inv1);
    }
}

// ---------------------------------------------------------------------------
// Prep: ONE kernel converts all weights + x; grid-stride, MLP=4.
// ---------------------------------------------------------------------------
#define G_WQ 1048576u
#define G_WK (G_WQ + 262144u)
#define G_WV (G_WK + 262144u)
#define G_WO (G_WV + 1048576u)
#define G_X  (G_WO + 2097152u)
#define NCONV_TH (G_X / 4)

__global__ void conv_all(const float* __restrict__ Wq, const float* __restrict__ Wk,
                         const float* __restrict__ Wv, const float* __restrict__ Wo,
                         const float* __restrict__ x,
                         __half* __restrict__ Wqkv, __half* __restrict__ Woh,
                         __half* __restrict__ xh, float qscale)
{
    uint32_t t = blockIdx.x * blockDim.x + threadIdx.x;
#pragma unroll
    for (int i = 0; i < 4; i++) {
        uint32_t g = t + (uint32_t)i * NCONV_TH;
        const float* src;
        __half* dst;
        uint32_t r, c;
        float sc = 1.f;
        if (g < G_WQ) {
            src = Wq + (size_t)g * 4;
            r = g >> 9; c = (g & 511) * 4;
            dst = Wqkv + (size_t)r * QKD3 + c;
            sc = qscale;
        } else if (g < G_WK) {
            uint32_t g2 = g - G_WQ;
            src = Wk + (size_t)g2 * 4;
            r = g2 >> 7; c = (g2 & 127) * 4;
            dst = Wqkv + (size_t)r * QKD3 + E_ + c;
        } else if (g < G_WV) {
            uint32_t g2 = g - G_WK;
            src = Wv + (size_t)g2 * 4;
            r = g2 >> 7; c = (g2 & 127) * 4;
            dst = Wqkv + (size_t)r * QKD3 + E_ + KVD_ + c;
        } else if (g < G_WO) {
            uint32_t g2 = g - G_WV;
            src = Wo + (size_t)g2 * 4;
            dst = Woh + (size_t)g2 * 4;
        } else {
            uint32_t g2 = g - G_WO;
            src = x + (size_t)g2 * 4;
            dst = xh + (size_t)g2 * 4;
        }
        float4 v = *reinterpret_cast<const float4*>(src);
        *reinterpret_cast<uint2*>(dst) =
            make_uint2(pack_h(v.x * sc, v.y * sc), pack_h(v.z * sc, v.w * sc));
    }
}

// ---------------------------------------------------------------------------
extern "C" void kernel_launch(void* const* d_in, const int* in_sizes, int n_in,
                              void* d_out, int out_size)
{
    const float* x  = (const float*)d_in[0];
    const float* Wq = (const float*)d_in[1];
    const float* Wk = (const float*)d_in[2];
    const float* Wv = (const float*)d_in[3];
    const float* Wo = (const float*)d_in[4];
    const float* bo = (const float*)d_in[5];
    float* out = (float*)d_out;

    __half *xh, *Wqkv, *Woh, *QKV, *Ah;
    cudaGetSymbolAddress((void**)&xh,   g_xh);
    cudaGetSymbolAddress((void**)&Wqkv, g_Wqkv);
    cudaGetSymbolAddress((void**)&Woh,  g_Woh);
    cudaGetSymbolAddress((void**)&QKV,  g_QKV);
    cudaGetSymbolAddress((void**)&Ah,   g_Ah);

    const int SMG = 4 * GSS2;   // 208896 -> 1 CTA/SM, 16 warps
    const int SMF = 3 * FSTG;   // 110592 -> 2 CTAs/SM
    cudaFuncSetAttribute(gemm_mma<0>, cudaFuncAttributeMaxDynamicSharedMemorySize, SMG);
    cudaFuncSetAttribute(gemm_mma<2>, cudaFuncAttributeMaxDynamicSharedMemorySize, SMG);
    cudaFuncSetAttribute(flash_attn, cudaFuncAttributeMaxDynamicSharedMemorySize, SMF);

    const float QSCALE = 0.125f * 1.44269504088896f;

    conv_all<<<NCONV_TH / 256, 256>>>(Wq, Wk, Wv, Wo, x, Wqkv, Woh, xh, QSCALE);

    // [Q|K|V] = x @ [Wq*s | Wk | Wv]  -> [4096, 3072]
    gemm_mma<2><<<dim3(QKD3 / 256, M_ / 128), 512, SMG>>>(
        xh, Wqkv, E_, QKD3, E_ / 64, nullptr, nullptr, QKV, QKD3);

    // fused attention -> Ah
    flash_attn<<<dim3(T_ / 128, HQ_, B_), 256, SMF>>>(QKV, Ah);

    // out = A @ Wo + bo
    gemm_mma<0><<<dim3(E_ / 256, M_ / 128), 512, SMG>>>(
        Ah, Woh, E_, E_, E_ / 64, out, bo, nullptr, E_);
}